// round 15
// baseline (speedup 1.0000x reference)
#include <cuda_runtime.h>
#include <math.h>
#include <stdint.h>

#define BATCH 8192
#define NRSS  12
#define NLED  256
#define NBLK  592   // 148 SMs * 4 CTAs
#define NT    128   // threads per CTA; each thread owns 2 LEDs

#define FMA2(acc, a, b)  asm("fma.rn.f32x2 %0, %1, %2, %0;" : "+l"(acc) : "l"(a), "l"(b))
#define ADD2(d, a, b)    asm("add.rn.f32x2 %0, %1, %2;" : "=l"(d) : "l"(a), "l"(b))
#define PACK2(d, lo, hi) asm("mov.b64 %0, {%1, %2};" : "=l"(d) : "f"(lo), "f"(hi))
#define UNPACK2(lo, hi, d) asm("mov.b64 {%0, %1}, %2;" : "=f"(lo), "=f"(hi) : "l"(d))

// ---- folded weights + per-batch precomputed tensors ----
__device__ float g_Wc[64 * 32];   // g_Wc[i*32+j] = sum_d qf_w2[.,d]*kp_w2[j,d], i-major
__device__ float g_v[64];
__device__ float g_bc[32];
__device__ float g_c0[1];
__device__ float g_Qhb[(size_t)BATCH * 12 * 32];  // cw-scaled reduced queries
__device__ float g_qcb[(size_t)BATCH * 12];
__device__ float g_invb[BATCH];

__global__ void fold_kernel(const float* __restrict__ qf_w2, const float* __restrict__ qf_b2,
                            const float* __restrict__ kp_w2, const float* __restrict__ kp_b2) {
    int e = blockIdx.x * blockDim.x + threadIdx.x;
    if (e < 2048) {
        int j = e >> 6, i = e & 63;
        float acc = 0.f;
        #pragma unroll 8
        for (int d = 0; d < 128; d++) acc += qf_w2[i * 128 + d] * kp_w2[j * 128 + d];
        g_Wc[i * 32 + j] = acc;
    }
    if (e < 64) {
        float acc = 0.f;
        #pragma unroll 8
        for (int d = 0; d < 128; d++) acc += qf_w2[e * 128 + d] * kp_b2[d];
        g_v[e] = acc;
    } else if (e < 96) {
        int j = e - 64;
        float acc = 0.f;
        #pragma unroll 8
        for (int d = 0; d < 128; d++) acc += qf_b2[d] * kp_w2[j * 128 + d];
        g_bc[j] = acc;
    } else if (e == 96) {
        float acc = 0.f;
        for (int d = 0; d < 128; d++) acc += qf_b2[d] * kp_b2[d];
        g_c0[0] = acc;
    }
}

// ---- chain kernel: one warp per batch, NO block barriers ----
// smem layout per warp (1024 floats): Ls[0..127], h1m[128..191], mc[192..223],
// rss[224..235], cw[236..247], inv[248], h1q[256 + q*64 + i]
__global__ __launch_bounds__(256)
void chain_kernel(const float* __restrict__ rss_t, const float* __restrict__ lstm,
                  const float* __restrict__ me_w1, const float* __restrict__ me_b1,
                  const float* __restrict__ me_w2, const float* __restrict__ me_b2,
                  const float* __restrict__ ci_w,  const float* __restrict__ ci_b,
                  const float* __restrict__ qf_w1, const float* __restrict__ qf_b1,
                  const float* __restrict__ ss_w,  const float* __restrict__ ss_b,
                  float* __restrict__ out) {
    __shared__ float buf[8][1024];
    int w = threadIdx.x >> 5, l = threadIdx.x & 31;
    int b = (blockIdx.x << 3) + w;
    float* S = buf[w];

    reinterpret_cast<float4*>(S)[l] =
        reinterpret_cast<const float4*>(lstm + (size_t)b * 128)[l];
    if (l < 12) S[224 + l] = rss_t[(size_t)b * NRSS + l];
    __syncwarp();

    // h1m[64]: lane computes j = l, l+32; me_w1 column reads coalesced, L1-hot
    #pragma unroll
    for (int h = 0; h < 2; h++) {
        int j = l + h * 32;
        float a0 = __ldg(&me_b1[j]), a1 = 0.f;
        #pragma unroll 8
        for (int i = 0; i < 128; i += 2) {
            a0 += S[i]     * __ldg(&me_w1[i * 64 + j]);
            a1 += S[i + 1] * __ldg(&me_w1[(i + 1) * 64 + j]);
        }
        S[128 + j] = fmaxf(a0 + a1, 0.f);
    }
    __syncwarp();

    // mc[32]: lane j = l
    {
        float a0 = __ldg(&me_b2[l]), a1 = 0.f;
        #pragma unroll 8
        for (int i = 0; i < 64; i += 2) {
            a0 += S[128 + i]     * __ldg(&me_w2[i * 32 + l]);
            a1 += S[128 + i + 1] * __ldg(&me_w2[(i + 1) * 32 + l]);
        }
        S[192 + l] = a0 + a1;
    }
    __syncwarp();

    // cw (lanes 0-11) + sigma (lane 12)
    if (l < 12) {
        float acc = __ldg(&ci_b[l]);
        #pragma unroll
        for (int i = 0; i < 32; i++) acc += S[192 + i] * __ldg(&ci_w[i * 12 + l]);
        float c = 1.f / (1.f + __expf(-acc));
        S[236 + l] = c;
        out[(size_t)BATCH * NRSS * NLED + (size_t)b * NRSS + l] = c;
    } else if (l == 12) {
        float x = __ldg(&ss_b[0]);
        #pragma unroll
        for (int i = 0; i < 32; i++) x += S[192 + i] * __ldg(&ss_w[i]);
        float sp = fmaxf(x, 0.f) + log1pf(__expf(-fabsf(x)));
        float sg = sp + 0.5f;
        S[248] = 0.5f / (sg * sg);
    }

    // h1q fold (all lanes): mc-dot shared across q; h1q[q][j] = relu(base + rss_q*w0)
    #pragma unroll
    for (int h = 0; h < 2; h++) {
        int j = l + h * 32;
        float d0 = 0.f, d1 = 0.f;
        #pragma unroll 8
        for (int i = 0; i < 32; i += 2) {
            d0 += S[192 + i]     * __ldg(&qf_w1[(i + 1) * 64 + j]);
            d1 += S[192 + i + 1] * __ldg(&qf_w1[(i + 2) * 64 + j]);
        }
        float w0 = __ldg(&qf_w1[j]);
        float base = __ldg(&qf_b1[j]) + d0 + d1;
        #pragma unroll
        for (int q = 0; q < NRSS; q++)
            S[256 + q * 64 + j] = fmaxf(fmaf(S[224 + q], w0, base), 0.f);
    }
    __syncwarp();

    // Qh[q][l] = cw[q]*(bc[l] + h1q[q] . Wc[:,l]); g_Wc coalesced across lanes
    float bj = g_bc[l];
    #pragma unroll
    for (int q = 0; q < NRSS; q++) {
        const float* hq = &S[256 + q * 64];
        float a0 = bj, a1 = 0.f;
        #pragma unroll 8
        for (int i = 0; i < 64; i += 2) {
            a0 += hq[i]     * __ldg(&g_Wc[i * 32 + l]);
            a1 += hq[i + 1] * __ldg(&g_Wc[(i + 1) * 32 + l]);
        }
        g_Qhb[((size_t)b * NRSS + q) * 32 + l] = (a0 + a1) * S[236 + q];
    }
    if (l < 12) {
        const float* hq = &S[256 + l * 64];
        float a0 = g_c0[0], a1 = 0.f;
        #pragma unroll 8
        for (int i = 0; i < 64; i += 2) { a0 += hq[i] * g_v[i]; a1 += hq[i + 1] * g_v[i + 1]; }
        g_qcb[(size_t)b * NRSS + l] = (a0 + a1) * S[236 + l];
    } else if (l == 12) {
        g_invb[b] = S[248];
    }
}

// ---- score kernel: persistent; per batch only loads + H-phase + scores + softmax ----
struct SMemS {
    float kp1 [11 * 32];    // row-major, ulonglong2 broadcast reads
    float Qh  [12 * 32];    // row-major, ulonglong2 broadcast reads
    float kpb1[32];
    float red [96];         // [0..47] warp maxes, [48..95] warp sums
    float qc  [NRSS];
    float prev[3];
    float inv2s2;
};

__device__ __forceinline__ float wredmax(float v) {
    #pragma unroll
    for (int o = 16; o; o >>= 1) v = fmaxf(v, __shfl_xor_sync(0xffffffffu, v, o));
    return v;
}
__device__ __forceinline__ float wredsum(float v) {
    #pragma unroll
    for (int o = 16; o; o >>= 1) v += __shfl_xor_sync(0xffffffffu, v, o);
    return v;
}

__global__ __launch_bounds__(NT, 4)
void score_kernel(const float* __restrict__ led_f,
                  const float* __restrict__ led_p,
                  const float* __restrict__ prevp,
                  const int*   __restrict__ fmask,
                  const float* __restrict__ kp_w1, const float* __restrict__ kp_b1,
                  float* __restrict__ out) {
    __shared__ __align__(16) SMemS sm;
    const int tid = threadIdx.x, lane = tid & 31, wid = tid >> 5;
    const float NEG_INF = __int_as_float(0xff800000);

    for (int idx = tid; idx < 11 * 32; idx += NT) sm.kp1[idx] = kp_w1[idx];
    if (tid < 32) sm.kpb1[tid] = kp_b1[tid];

    uint32_t mba = 0, mbb = 0;
    #pragma unroll
    for (int q = 0; q < NRSS; q++) {
        mba |= (fmask[q * NLED + tid] != 0 ? 1u : 0u) << q;
        mbb |= (fmask[q * NLED + tid + 128] != 0 ? 1u : 0u) << q;
    }
    __syncthreads();

    for (int b = blockIdx.x; b < BATCH; b += gridDim.x) {
        // prefetch this thread's 2 LEDs
        const float4* lfa = reinterpret_cast<const float4*>(led_f + ((size_t)b * NLED + tid) * 8);
        const float4* lfb = reinterpret_cast<const float4*>(led_f + ((size_t)b * NLED + tid + 128) * 8);
        float4 fa0 = lfa[0], fa1 = lfa[1];
        float4 fb0 = lfb[0], fb1 = lfb[1];
        const float* ppa = led_p + ((size_t)b * NLED + tid) * 3;
        const float* ppb = led_p + ((size_t)b * NLED + tid + 128) * 3;
        float pax = ppa[0], pay = ppa[1], paz = ppa[2];
        float pbx = ppb[0], pby = ppb[1], pbz = ppb[2];

        // stage precomputed Qh/qc/inv/prev (coalesced)
        {
            const float* qb = &g_Qhb[(size_t)b * 384];
            sm.Qh[tid] = qb[tid];
            sm.Qh[tid + 128] = qb[tid + 128];
            sm.Qh[tid + 256] = qb[tid + 256];
        }
        if (tid < 12) sm.qc[tid] = g_qcb[(size_t)b * NRSS + tid];
        else if (tid == 12) sm.inv2s2 = g_invb[b];
        else if (tid < 16) sm.prev[tid - 13] = prevp[(size_t)b * 3 + (tid - 13)];
        __syncthreads();

        // ---- packed f32x2 MLP ----
        float kina[11] = {fa0.x, fa0.y, fa0.z, fa0.w, fa1.x, fa1.y, fa1.z, fa1.w, pax, pay, paz};
        float kinb[11] = {fb0.x, fb0.y, fb0.z, fb0.w, fb1.x, fb1.y, fb1.z, fb1.w, pbx, pby, pbz};
        unsigned long long hA[16], hB[16];
        {
            const ulonglong2* bp = (const ulonglong2*)sm.kpb1;
            #pragma unroll
            for (int m = 0; m < 8; m++) {
                ulonglong2 v = bp[m];
                hA[2 * m] = v.x; hA[2 * m + 1] = v.y;
                hB[2 * m] = v.x; hB[2 * m + 1] = v.y;
            }
        }
        #pragma unroll
        for (int i = 0; i < 11; i++) {
            unsigned long long ta2, tb2;
            PACK2(ta2, kina[i], kina[i]);
            PACK2(tb2, kinb[i], kinb[i]);
            const ulonglong2* wp = (const ulonglong2*)&sm.kp1[i * 32];
            #pragma unroll
            for (int m = 0; m < 8; m++) {
                ulonglong2 w = wp[m];
                FMA2(hA[2 * m], w.x, ta2); FMA2(hA[2 * m + 1], w.y, ta2);
                FMA2(hB[2 * m], w.x, tb2); FMA2(hB[2 * m + 1], w.y, tb2);
            }
        }
        #pragma unroll
        for (int m = 0; m < 16; m++) {
            float lo, hi;
            UNPACK2(lo, hi, hA[m]); PACK2(hA[m], fmaxf(lo, 0.f), fmaxf(hi, 0.f));
            UNPACK2(lo, hi, hB[m]); PACK2(hB[m], fmaxf(lo, 0.f), fmaxf(hi, 0.f));
        }

        float dax = sm.prev[0] - pax, day = sm.prev[1] - pay, daz = sm.prev[2] - paz;
        float dbx = sm.prev[0] - pbx, dby = sm.prev[1] - pby, dbz = sm.prev[2] - pbz;
        float dba = (dax * dax + day * day + daz * daz) * sm.inv2s2;
        float dbb = (dbx * dbx + dby * dby + dbz * dbz) * sm.inv2s2;

        // ---- packed f32x2 scores ----
        float sa[NRSS], sb[NRSS];
        #pragma unroll
        for (int q = 0; q < NRSS; q++) {
            unsigned long long a0 = 0ull, a1 = 0ull, b0 = 0ull, b1 = 0ull;
            const ulonglong2* wp = (const ulonglong2*)&sm.Qh[q * 32];
            #pragma unroll
            for (int m = 0; m < 8; m++) {
                ulonglong2 w = wp[m];
                FMA2(a0, w.x, hA[2 * m]); FMA2(a1, w.y, hA[2 * m + 1]);
                FMA2(b0, w.x, hB[2 * m]); FMA2(b1, w.y, hB[2 * m + 1]);
            }
            unsigned long long accA, accB;
            ADD2(accA, a0, a1); ADD2(accB, b0, b1);
            float alo, ahi, blo, bhi;
            UNPACK2(alo, ahi, accA); UNPACK2(blo, bhi, accB);
            float qcq = sm.qc[q];
            float aa = qcq + (alo + ahi);
            float ab = qcq + (blo + bhi);
            sa[q] = ((mba >> q) & 1) ? (aa - dba) : NEG_INF;
            sb[q] = ((mbb >> q) & 1) ? (ab - dbb) : NEG_INF;
        }

        // softmax over 256 LEDs: 2 barriers, local 4-partial reduce
        #pragma unroll
        for (int q = 0; q < NRSS; q++) {
            float m = wredmax(fmaxf(sa[q], sb[q]));
            if (lane == 0) sm.red[q * 4 + wid] = m;
        }
        __syncthreads();
        #pragma unroll
        for (int q = 0; q < NRSS; q++) {
            float m = fmaxf(fmaxf(sm.red[q * 4], sm.red[q * 4 + 1]),
                            fmaxf(sm.red[q * 4 + 2], sm.red[q * 4 + 3]));
            float ea = __expf(sa[q] - m), eb = __expf(sb[q] - m);
            sa[q] = ea; sb[q] = eb;
            float s = wredsum(ea + eb);
            if (lane == 0) sm.red[48 + q * 4 + wid] = s;
        }
        __syncthreads();
        #pragma unroll
        for (int q = 0; q < NRSS; q++) {
            float s = (sm.red[48 + q * 4] + sm.red[48 + q * 4 + 1]) +
                      (sm.red[48 + q * 4 + 2] + sm.red[48 + q * 4 + 3]);
            float inv = __frcp_rn(s);
            size_t base = ((size_t)b * NRSS + q) << 8;
            out[base + tid] = sa[q] * inv;
            out[base + tid + 128] = sb[q] * inv;
        }
        // next-iter writes (Qh/qc/prev/inv) are disjoint from red[48..] reads above
        // and separated from this iter's Qh reads by the two softmax barriers.
    }
}

extern "C" void kernel_launch(void* const* d_in, const int* in_sizes, int n_in,
                              void* d_out, int out_size) {
    (void)in_sizes; (void)n_in; (void)out_size;
    const float* rss_t  = (const float*)d_in[0];
    const float* led_f  = (const float*)d_in[1];
    const float* led_p  = (const float*)d_in[2];
    const float* prevp  = (const float*)d_in[3];
    const int*   fmask  = (const int*)  d_in[4];
    const float* lstm   = (const float*)d_in[5];
    const float* me_w1  = (const float*)d_in[6];
    const float* me_b1  = (const float*)d_in[7];
    const float* me_w2  = (const float*)d_in[8];
    const float* me_b2  = (const float*)d_in[9];
    const float* ci_w   = (const float*)d_in[10];
    const float* ci_b   = (const float*)d_in[11];
    const float* qf_w1  = (const float*)d_in[12];
    const float* qf_b1  = (const float*)d_in[13];
    const float* qf_w2  = (const float*)d_in[14];
    const float* qf_b2  = (const float*)d_in[15];
    const float* kp_w1  = (const float*)d_in[16];
    const float* kp_b1  = (const float*)d_in[17];
    const float* kp_w2  = (const float*)d_in[18];
    const float* kp_b2  = (const float*)d_in[19];
    const float* ss_w   = (const float*)d_in[20];
    const float* ss_b   = (const float*)d_in[21];
    float* out = (float*)d_out;

    fold_kernel<<<8, 256>>>(qf_w2, qf_b2, kp_w2, kp_b2);
    chain_kernel<<<BATCH / 8, 256>>>(rss_t, lstm, me_w1, me_b1, me_w2, me_b2,
                                     ci_w, ci_b, qf_w1, qf_b1, ss_w, ss_b, out);
    score_kernel<<<NBLK, NT>>>(led_f, led_p, prevp, fmask, kp_w1, kp_b1, out);
}

// round 17
// speedup vs baseline: 1.2589x; 1.2589x over previous
#include <cuda_runtime.h>
#include <math.h>
#include <stdint.h>

#define BATCH 8192
#define NRSS  12
#define NLED  256
#define NBLK  592   // 148 SMs * 4 CTAs
#define NT    128   // threads per CTA; each thread owns 2 LEDs

#define FMA2(acc, a, b)  asm("fma.rn.f32x2 %0, %1, %2, %0;" : "+l"(acc) : "l"(a), "l"(b))
#define ADD2(d, a, b)    asm("add.rn.f32x2 %0, %1, %2;" : "=l"(d) : "l"(a), "l"(b))
#define PACK2(d, lo, hi) asm("mov.b64 %0, {%1, %2};" : "=l"(d) : "f"(lo), "f"(hi))
#define UNPACK2(lo, hi, d) asm("mov.b64 {%0, %1}, %2;" : "=f"(lo), "=f"(hi) : "l"(d))

// ---- folded weights (computed once per launch by fold_kernel) ----
__device__ float g_WcT[32 * 64];  // WcT[j][i] = sum_d qf_w2[i,d]*kp_w2[j,d]
__device__ float g_v[64];         // v[i] = sum_d qf_w2[i,d]*kp_b2[d]
__device__ float g_bc[32];        // bc[j] = sum_d qf_b2[d]*kp_w2[j,d]
__device__ float g_c0[1];         // c0 = qf_b2 . kp_b2

// Parallel fold: 4 threads per output (32-MAC partials + quartet shfl reduce).
// Blocks 0..31: g_WcT (64 outputs each). Block 32: g_v. Block 33: g_bc + g_c0.
__global__ void fold_kernel(const float* __restrict__ qf_w2, const float* __restrict__ qf_b2,
                            const float* __restrict__ kp_w2, const float* __restrict__ kp_b2) {
    const int quarter = threadIdx.x & 3;
    const int o = threadIdx.x >> 2;      // 0..63 within block
    const int d0 = quarter * 32;
    const unsigned qm = 0xFu << ((threadIdx.x & 31) & ~3);  // quartet mask

    if (blockIdx.x < 32) {
        int e = blockIdx.x * 64 + o;     // 0..2047
        int j = e >> 6, i = e & 63;
        float acc = 0.f;
        #pragma unroll
        for (int d = 0; d < 32; d++) acc += qf_w2[i * 128 + d0 + d] * kp_w2[j * 128 + d0 + d];
        acc += __shfl_xor_sync(qm, acc, 1);
        acc += __shfl_xor_sync(qm, acc, 2);
        if (quarter == 0) g_WcT[e] = acc;
    } else if (blockIdx.x == 32) {
        float acc = 0.f;
        #pragma unroll
        for (int d = 0; d < 32; d++) acc += qf_w2[o * 128 + d0 + d] * kp_b2[d0 + d];
        acc += __shfl_xor_sync(qm, acc, 1);
        acc += __shfl_xor_sync(qm, acc, 2);
        if (quarter == 0) g_v[o] = acc;
    } else {
        if (o < 32) {
            float acc = 0.f;
            #pragma unroll
            for (int d = 0; d < 32; d++) acc += qf_b2[d0 + d] * kp_w2[o * 128 + d0 + d];
            acc += __shfl_xor_sync(qm, acc, 1);
            acc += __shfl_xor_sync(qm, acc, 2);
            if (quarter == 0) g_bc[o] = acc;
        } else if (o == 32) {
            float acc = 0.f;
            #pragma unroll
            for (int d = 0; d < 32; d++) acc += qf_b2[d0 + d] * kp_b2[d0 + d];
            acc += __shfl_xor_sync(qm, acc, 1);
            acc += __shfl_xor_sync(qm, acc, 2);
            if (quarter == 0) g_c0[0] = acc;
        }
    }
}

// ---- shared memory layout; ~51KB -> 4 CTAs/SM ----
// me1T: row stride 136 floats; element i of row j at j*136 + i + (i>=64 ? 4 : 0)
// -> half-dot split (half at +0 / +68) is bank-conflict-free for LDS.128.
struct SMem {
    float me1T[64 * 136];
    float WcT [32 * 68];    // conflict-free f4/u2 (stride 17 f4)
    float h1q [12 * 68];
    float kp1 [11 * 32];    // row-major, ulonglong2 broadcast reads
    float Qh  [12 * 32];    // row-major, ulonglong2 broadcast reads
    float kpb1[32];
    float Ls  [128];
    float mc  [32];
    float h1m [64];
    float red [96];         // [0..47] warp maxes, [48..95] warp sums
    float rss [NRSS];
    float cw  [NRSS];
    float qc  [NRSS];
    float prev[3];
    float inv2s2;
};

__device__ __forceinline__ float wredmax(float v) {
    #pragma unroll
    for (int o = 16; o; o >>= 1) v = fmaxf(v, __shfl_xor_sync(0xffffffffu, v, o));
    return v;
}
__device__ __forceinline__ float wredsum(float v) {
    #pragma unroll
    for (int o = 16; o; o >>= 1) v += __shfl_xor_sync(0xffffffffu, v, o);
    return v;
}
__device__ __forceinline__ float dot4(float4 a, float4 b) {
    return a.x * b.x + a.y * b.y + a.z * b.z + a.w * b.w;
}

__global__ __launch_bounds__(NT, 4)
void cah_kernel(const float* __restrict__ rss_t,
                const float* __restrict__ led_f,
                const float* __restrict__ led_p,
                const float* __restrict__ prevp,
                const int*   __restrict__ fmask,
                const float* __restrict__ lstm,
                const float* __restrict__ me_w1, const float* __restrict__ me_b1,
                const float* __restrict__ me_w2, const float* __restrict__ me_b2,
                const float* __restrict__ ci_w,  const float* __restrict__ ci_b,
                const float* __restrict__ qf_w1, const float* __restrict__ qf_b1,
                const float* __restrict__ kp_w1, const float* __restrict__ kp_b1,
                const float* __restrict__ ss_w,  const float* __restrict__ ss_b,
                float* __restrict__ out) {
    extern __shared__ __align__(16) float smraw[];
    SMem& sm = *reinterpret_cast<SMem*>(smraw);
    const int tid = threadIdx.x, lane = tid & 31, wid = tid >> 5;
    const float NEG_INF = __int_as_float(0xff800000);

    // ---- stage weights once per CTA ----
    for (int idx = tid; idx < 128 * 64; idx += NT) {
        int i = idx >> 6, j = idx & 63;
        sm.me1T[j * 136 + i + ((i >> 6) << 2)] = me_w1[idx];  // +4 gap after first 64
    }
    for (int idx = tid; idx < 32 * 64;  idx += NT) { int j = idx >> 6, i = idx & 63; sm.WcT[j * 68 + i] = g_WcT[idx]; }
    for (int idx = tid; idx < 11 * 32;  idx += NT) sm.kp1[idx] = kp_w1[idx];
    if (tid < 32) sm.kpb1[tid] = kp_b1[tid];

    // per-thread mask bits for LEDs ka=tid, kb=tid+128
    uint32_t mba = 0, mbb = 0;
    #pragma unroll
    for (int q = 0; q < NRSS; q++) {
        mba |= (fmask[q * NLED + tid] != 0 ? 1u : 0u) << q;
        mbb |= (fmask[q * NLED + tid + 128] != 0 ? 1u : 0u) << q;
    }
    __syncthreads();

    for (int b = blockIdx.x; b < BATCH; b += gridDim.x) {
        // prefetch this thread's 2 LEDs (overlaps all the small phases)
        const float4* lfa = reinterpret_cast<const float4*>(led_f + ((size_t)b * NLED + tid) * 8);
        const float4* lfb = reinterpret_cast<const float4*>(led_f + ((size_t)b * NLED + tid + 128) * 8);
        float4 fa0 = lfa[0], fa1 = lfa[1];
        float4 fb0 = lfb[0], fb1 = lfb[1];
        const float* ppa = led_p + ((size_t)b * NLED + tid) * 3;
        const float* ppb = led_p + ((size_t)b * NLED + tid + 128) * 3;
        float pax = ppa[0], pay = ppa[1], paz = ppa[2];
        float pbx = ppb[0], pby = ppb[1], pbz = ppb[2];

        if (tid < 32) {
            reinterpret_cast<float4*>(sm.Ls)[tid] =
                reinterpret_cast<const float4*>(lstm + (size_t)b * 128)[tid];
        } else if (tid < 44) sm.rss[tid - 32] = rss_t[(size_t)b * NRSS + (tid - 32)];
        else if (tid < 47)  sm.prev[tid - 44] = prevp[(size_t)b * 3 + (tid - 44)];
        __syncthreads();

        // h1m = relu(Ls @ me_w1 + b1) [64]; 2 threads per output (half-dots in
        // FMA2, shfl-combined) -> chain depth halved. Conflict-free per layout.
        {
            int j = tid >> 1, half = tid & 1;
            const ulonglong2* Lp = reinterpret_cast<const ulonglong2*>(sm.Ls) + half * 16;
            const ulonglong2* Wp = reinterpret_cast<const ulonglong2*>(&sm.me1T[j * 136]) + half * 17;
            unsigned long long a0 = 0ull, a1 = 0ull;
            #pragma unroll
            for (int k = 0; k < 16; k += 2) {
                ulonglong2 L0 = Lp[k], L1 = Lp[k + 1];
                ulonglong2 W0 = Wp[k], W1 = Wp[k + 1];
                FMA2(a0, L0.x, W0.x); FMA2(a1, L0.y, W0.y);
                FMA2(a0, L1.x, W1.x); FMA2(a1, L1.y, W1.y);
            }
            unsigned long long s2; ADD2(s2, a0, a1);
            float lo, hi; UNPACK2(lo, hi, s2);
            float part = lo + hi;
            part += __shfl_xor_sync(0xffffffffu, part, 1);
            if (half == 0) sm.h1m[j] = fmaxf(part + __ldg(&me_b1[j]), 0.f);
        }
        __syncthreads();

        // mc = h1m @ me_w2 + b2 [32]; 4 threads per output, shfl-combined
        {
            int j = tid >> 2, q4 = tid & 3;
            int i0 = q4 * 16;
            float a = 0.f, a1 = 0.f;
            #pragma unroll
            for (int k = 0; k < 16; k += 2) {
                a  += sm.h1m[i0 + k]     * __ldg(&me_w2[(i0 + k) * 32 + j]);
                a1 += sm.h1m[i0 + k + 1] * __ldg(&me_w2[(i0 + k + 1) * 32 + j]);
            }
            a += a1;
            a += __shfl_xor_sync(0xffffffffu, a, 1);
            a += __shfl_xor_sync(0xffffffffu, a, 2);
            if (q4 == 0) sm.mc[j] = a + __ldg(&me_b2[j]);
        }
        __syncthreads();

        // cw/sigma on warp 2 (tid 64..76) CONCURRENT with h1q fold on warps 0-1
        if (tid >= 64 && tid < 76) {
            int q = tid - 64;
            float acc = __ldg(&ci_b[q]);
            #pragma unroll
            for (int i = 0; i < 32; i++) acc += sm.mc[i] * __ldg(&ci_w[i * 12 + q]);
            float c = 1.f / (1.f + __expf(-acc));
            sm.cw[q] = c;
            out[(size_t)BATCH * NRSS * NLED + (size_t)b * NRSS + q] = c;
        } else if (tid == 76) {
            float x = __ldg(&ss_b[0]);
            #pragma unroll
            for (int i = 0; i < 32; i++) x += sm.mc[i] * __ldg(&ss_w[i]);
            float sp = fmaxf(x, 0.f) + log1pf(__expf(-fabsf(x)));
            float sg = sp + 0.5f;
            sm.inv2s2 = 0.5f / (sg * sg);
        }

        // h1q ALGEBRAIC FOLD (tid<64): the mc-dot is identical across all 12 q.
        if (tid < 64) {
            int j = tid;
            float d0 = 0.f, d1 = 0.f;
            #pragma unroll 8
            for (int i = 0; i < 32; i += 2) {
                d0 += sm.mc[i]     * __ldg(&qf_w1[(i + 1) * 64 + j]);
                d1 += sm.mc[i + 1] * __ldg(&qf_w1[(i + 2) * 64 + j]);
            }
            float w0 = __ldg(&qf_w1[j]);
            float base = __ldg(&qf_b1[j]) + d0 + d1;
            #pragma unroll
            for (int q = 0; q < NRSS; q++)
                sm.h1q[q * 68 + j] = fmaxf(fmaf(sm.rss[q], w0, base), 0.f);
        }
        __syncthreads();

        // Qh[q][32] = cw[q]*(h1q @ Wc + bc); FMA2 over paired floats
        {
            int j = tid & 31, qo = tid >> 5;
            float bj = g_bc[j];
            const ulonglong2* r2 = reinterpret_cast<const ulonglong2*>(&sm.WcT[j * 68]);
            #pragma unroll
            for (int p = 0; p < 3; p++) {
                int q = 4 * p + qo;
                const ulonglong2* hq2 = reinterpret_cast<const ulonglong2*>(&sm.h1q[q * 68]);
                unsigned long long a0 = 0ull, a1 = 0ull;
                #pragma unroll
                for (int m = 0; m < 16; m += 2) {
                    ulonglong2 w0 = r2[m], w1 = r2[m + 1];
                    ulonglong2 h0 = hq2[m], h1 = hq2[m + 1];
                    FMA2(a0, w0.x, h0.x); FMA2(a1, w0.y, h0.y);
                    FMA2(a0, w1.x, h1.x); FMA2(a1, w1.y, h1.y);
                }
                unsigned long long s2; ADD2(s2, a0, a1);
                float lo, hi; UNPACK2(lo, hi, s2);
                sm.Qh[(q << 5) + j] = (bj + lo + hi) * sm.cw[q];
            }
            if (tid < 12) {  // qc[q]
                const float4* hq = reinterpret_cast<const float4*>(&sm.h1q[tid * 68]);
                const float4* v4 = reinterpret_cast<const float4*>(g_v);
                float a0 = g_c0[0], a1 = 0.f;
                #pragma unroll
                for (int i = 0; i < 16; i += 2) { a0 += dot4(hq[i], v4[i]); a1 += dot4(hq[i + 1], v4[i + 1]); }
                sm.qc[tid] = (a0 + a1) * sm.cw[tid];
            }
        }
        __syncthreads();

        // ---- packed f32x2 MLP: hA[m]=(ha_{2m},ha_{2m+1}), hB likewise ----
        float kina[11] = {fa0.x, fa0.y, fa0.z, fa0.w, fa1.x, fa1.y, fa1.z, fa1.w, pax, pay, paz};
        float kinb[11] = {fb0.x, fb0.y, fb0.z, fb0.w, fb1.x, fb1.y, fb1.z, fb1.w, pbx, pby, pbz};
        unsigned long long hA[16], hB[16];
        {
            const ulonglong2* bp = (const ulonglong2*)sm.kpb1;
            #pragma unroll
            for (int m = 0; m < 8; m++) {
                ulonglong2 v = bp[m];
                hA[2 * m] = v.x; hA[2 * m + 1] = v.y;
                hB[2 * m] = v.x; hB[2 * m + 1] = v.y;
            }
        }
        #pragma unroll
        for (int i = 0; i < 11; i++) {
            unsigned long long ta2, tb2;
            PACK2(ta2, kina[i], kina[i]);
            PACK2(tb2, kinb[i], kinb[i]);
            const ulonglong2* wp = (const ulonglong2*)&sm.kp1[i * 32];
            #pragma unroll
            for (int m = 0; m < 8; m++) {
                ulonglong2 w = wp[m];
                FMA2(hA[2 * m], w.x, ta2); FMA2(hA[2 * m + 1], w.y, ta2);
                FMA2(hB[2 * m], w.x, tb2); FMA2(hB[2 * m + 1], w.y, tb2);
            }
        }
        // relu on packed pairs
        #pragma unroll
        for (int m = 0; m < 16; m++) {
            float lo, hi;
            UNPACK2(lo, hi, hA[m]); PACK2(hA[m], fmaxf(lo, 0.f), fmaxf(hi, 0.f));
            UNPACK2(lo, hi, hB[m]); PACK2(hB[m], fmaxf(lo, 0.f), fmaxf(hi, 0.f));
        }

        float dax = sm.prev[0] - pax, day = sm.prev[1] - pay, daz = sm.prev[2] - paz;
        float dbx = sm.prev[0] - pbx, dby = sm.prev[1] - pby, dbz = sm.prev[2] - pbz;
        float dba = (dax * dax + day * day + daz * daz) * sm.inv2s2;
        float dbb = (dbx * dbx + dby * dby + dbz * dbz) * sm.inv2s2;

        // ---- packed f32x2 scores ----
        float sa[NRSS], sb[NRSS];
        #pragma unroll
        for (int q = 0; q < NRSS; q++) {
            unsigned long long a0 = 0ull, a1 = 0ull, b0 = 0ull, b1 = 0ull;
            const ulonglong2* wp = (const ulonglong2*)&sm.Qh[q * 32];
            #pragma unroll
            for (int m = 0; m < 8; m++) {
                ulonglong2 w = wp[m];
                FMA2(a0, w.x, hA[2 * m]); FMA2(a1, w.y, hA[2 * m + 1]);
                FMA2(b0, w.x, hB[2 * m]); FMA2(b1, w.y, hB[2 * m + 1]);
            }
            unsigned long long accA, accB;
            ADD2(accA, a0, a1); ADD2(accB, b0, b1);
            float alo, ahi, blo, bhi;
            UNPACK2(alo, ahi, accA); UNPACK2(blo, bhi, accB);
            float qcq = sm.qc[q];
            float aa = qcq + (alo + ahi);
            float ab = qcq + (blo + bhi);
            sa[q] = ((mba >> q) & 1) ? (aa - dba) : NEG_INF;
            sb[q] = ((mbb >> q) & 1) ? (ab - dbb) : NEG_INF;
        }

        // softmax over 256 LEDs: 2 barriers, local 4-partial reduce
        #pragma unroll
        for (int q = 0; q < NRSS; q++) {
            float m = wredmax(fmaxf(sa[q], sb[q]));
            if (lane == 0) sm.red[q * 4 + wid] = m;
        }
        __syncthreads();
        #pragma unroll
        for (int q = 0; q < NRSS; q++) {
            float m = fmaxf(fmaxf(sm.red[q * 4], sm.red[q * 4 + 1]),
                            fmaxf(sm.red[q * 4 + 2], sm.red[q * 4 + 3]));
            float ea = __expf(sa[q] - m), eb = __expf(sb[q] - m);
            sa[q] = ea; sb[q] = eb;
            float s = wredsum(ea + eb);
            if (lane == 0) sm.red[48 + q * 4 + wid] = s;
        }
        __syncthreads();
        #pragma unroll
        for (int q = 0; q < NRSS; q++) {
            float s = (sm.red[48 + q * 4] + sm.red[48 + q * 4 + 1]) +
                      (sm.red[48 + q * 4 + 2] + sm.red[48 + q * 4 + 3]);
            float inv = __frcp_rn(s);
            size_t base = ((size_t)b * NRSS + q) << 8;
            out[base + tid] = sa[q] * inv;
            out[base + tid + 128] = sb[q] * inv;
        }
        // next-iter load phase writes Ls/rss/prev, all last read before the two
        // softmax barriers above; red[48..] reads are separated from next-iter
        // red[48..] writes by the load barrier + max barrier. No trailing sync.
    }
}

extern "C" void kernel_launch(void* const* d_in, const int* in_sizes, int n_in,
                              void* d_out, int out_size) {
    (void)in_sizes; (void)n_in; (void)out_size;
    const float* rss_t  = (const float*)d_in[0];
    const float* led_f  = (const float*)d_in[1];
    const float* led_p  = (const float*)d_in[2];
    const float* prevp  = (const float*)d_in[3];
    const int*   fmask  = (const int*)  d_in[4];
    const float* lstm   = (const float*)d_in[5];
    const float* me_w1  = (const float*)d_in[6];
    const float* me_b1  = (const float*)d_in[7];
    const float* me_w2  = (const float*)d_in[8];
    const float* me_b2  = (const float*)d_in[9];
    const float* ci_w   = (const float*)d_in[10];
    const float* ci_b   = (const float*)d_in[11];
    const float* qf_w1  = (const float*)d_in[12];
    const float* qf_b1  = (const float*)d_in[13];
    const float* qf_w2  = (const float*)d_in[14];
    const float* qf_b2  = (const float*)d_in[15];
    const float* kp_w1  = (const float*)d_in[16];
    const float* kp_b1  = (const float*)d_in[17];
    const float* kp_w2  = (const float*)d_in[18];
    const float* kp_b2  = (const float*)d_in[19];
    const float* ss_w   = (const float*)d_in[20];
    const float* ss_b   = (const float*)d_in[21];
    float* out = (float*)d_out;

    static int smem_set = 0;
    if (!smem_set) {
        cudaFuncSetAttribute(cah_kernel, cudaFuncAttributeMaxDynamicSharedMemorySize,
                             (int)sizeof(SMem));
        smem_set = 1;
    }

    fold_kernel<<<34, 256>>>(qf_w2, qf_b2, kp_w2, kp_b2);
    cah_kernel<<<NBLK, NT, sizeof(SMem)>>>(rss_t, led_f, led_p, prevp, fmask, lstm,
                                           me_w1, me_b1, me_w2, me_b2, ci_w, ci_b,
                                           qf_w1, qf_b1, kp_w1, kp_b1, ss_w, ss_b, out);
}